// round 13
// baseline (speedup 1.0000x reference)
#include <cuda_runtime.h>
#include <cuda_fp16.h>

// WeightedDiceLoss (sm_103a) — balanced persistent-band version.
// Grid = 2*SMs; CTA i takes contiguous 16-row bands [i*B/G,(i+1)*B/G).
// fp16 swizzled hsum ring (RING=64), ONE barrier per 16-row chunk,
// local 3-lane hsum producer.
// weight = 1 + 5*|boxavg31(target) - target|, zero pad, /961
// out = 1 - (2*sum(in*t*w) + 1) / (sum(in*w) + sum(t*w) + 1)

#define Wd    512
#define Hd    512
#define HALO  15
#define RING  64                   // fp16 rows of 1KB -> 64KB
#define INV_KK2 (1.0f/961.0f)

__device__ float g_part[3 * 1024];
__device__ unsigned int g_count = 0;

__global__ __launch_bounds__(512, 2)
void wdice_main(const float* __restrict__ input,
                const float* __restrict__ target,
                int nBands,                       // total 16-row bands (img*32)
                float* __restrict__ out)
{
    extern __shared__ __half HS[];          // [RING][512] swizzled fp16 hsum
    const int tid  = threadIdx.x;
    const int wid  = tid >> 5;
    const int lane = tid & 31;
    const int G    = gridDim.x;

    // consumer column + fixed swizzled byte offset
    const int c = tid;
    const int u = c >> 3;
    const int qoff = (u ^ ((u >> 3) & 7)) * 16 + (c & 7) * 2;
    const char* HSb = (const char*)HS;

    float aI = 0.f, aA = 0.f, aB = 0.f;

    int b0 = (int)(((long long)blockIdx.x * nBands) / G);
    const int b1 = (int)(((long long)(blockIdx.x + 1) * nBands) / G);

    while (b0 < b1) {
        const int img    = b0 >> 5;                    // 32 bands per image
        const int segEnd = min(b1, (img + 1) << 5);
        const int nb     = segEnd - b0;                // chunks in this segment
        const int r0     = (b0 & 31) * 16;             // first output row
        const int R      = nb * 16;                    // output rows in segment
        const size_t imgOff = (size_t)img * (size_t)(Hd * Wd);

        // Producer: hsum of target row (r0-15+pr+wid) -> fp16 swizzled slot.
        auto produce = [&](int pr) {
            const int j = pr + wid;                    // 16 rows per call
            if (j >= R + 2 * HALO) return;
            const int gr = r0 - HALO + j;
            uint4* dstRow = (uint4*)((char*)HS + (size_t)(j & (RING - 1)) * 1024);
            const int key = (lane >> 2) & 7;
            if (gr < 0 || gr >= Hd) {
                const uint4 z = make_uint4(0, 0, 0, 0);
                dstRow[(2 * lane)     ^ key] = z;
                dstRow[(2 * lane + 1) ^ key] = z;
                return;
            }
            float p[16];
            const float4* row = (const float4*)(target + imgOff + (size_t)gr * Wd);
            #pragma unroll
            for (int q = 0; q < 4; q++) {
                float4 f = row[lane * 4 + q];
                p[4*q+0] = f.x; p[4*q+1] = f.y; p[4*q+2] = f.z; p[4*q+3] = f.w;
            }
            #pragma unroll
            for (int i = 1; i < 16; i++) p[i] += p[i-1];
            const float T  = p[15];
            float Tp = __shfl_up_sync(0xffffffffu, T, 1);
            if (lane == 0) Tp = 0.f;
            const float base = Tp + T;
            float h[16];
            #pragma unroll
            for (int i = 0; i < 16; i++) {
                float pm = __shfl_up_sync(0xffffffffu, p[i], 1);
                if (lane == 0) pm = 0.f;
                h[i] = base - pm;
            }
            #pragma unroll
            for (int i = 1; i < 16; i++) {
                float pp = __shfl_down_sync(0xffffffffu, p[i-1], 1);
                if (lane == 31) pp = 0.f;
                h[i] += pp;
            }
            unsigned up[8];
            #pragma unroll
            for (int q = 0; q < 8; q++) {
                __half2 hh = __floats2half2_rn(h[2*q], h[2*q+1]);
                up[q] = *reinterpret_cast<unsigned*>(&hh);
            }
            dstRow[(2 * lane)     ^ key] = make_uint4(up[0], up[1], up[2], up[3]);
            dstRow[(2 * lane + 1) ^ key] = make_uint4(up[4], up[5], up[6], up[7]);
        };

        // Prime ring rows 0..63 (guarded internally).
        produce(0); produce(16); produce(32); produce(48);
        __syncthreads();

        float vsum = 0.f;
        #pragma unroll
        for (int j = 0; j <= 2 * HALO; j++)
            vsum += __half2float(*(const __half*)(HSb + j * 1024 + qoff));

        const float* inp = input  + imgOff + (size_t)r0 * Wd + c;
        const float* tgt = target + imgOff + (size_t)r0 * Wd + c;

        for (int ch = 0; ch < nb; ch++) {
            const int kb = ch * 16;
            #pragma unroll
            for (int kk = 0; kk < 16; kk++) {
                const int k = kb + kk;
                const float t  = tgt[k * Wd];
                const float in = inp[k * Wd];
                const float w  = fmaf(5.f, fabsf(fmaf(vsum, INV_KK2, -t)), 1.f);
                const float tw = t * w;
                aI = fmaf(in, tw, aI);
                aA = fmaf(in, w,  aA);
                aB += tw;

                if (k + 1 < R) {
                    const int ja = (k + 31) & (RING - 1);
                    const int js = k & (RING - 1);
                    const float a = __half2float(*(const __half*)(HSb + ja * 1024 + qoff));
                    const float s = __half2float(*(const __half*)(HSb + js * 1024 + qoff));
                    vsum += (a - s);
                }
            }
            __syncthreads();               // WAR for produce; RAW slack = 2 chunks
            if (ch + 1 < nb)
                produce(64 + kb);          // rows first read at chunk ch+2
        }
        // threads all past the final consume barrier; ring reusable next segment
        b0 = segEnd;
    }

    // ---- Block reduction (fixed order -> deterministic)
    #pragma unroll
    for (int o = 16; o > 0; o >>= 1) {
        aI += __shfl_down_sync(0xffffffffu, aI, o);
        aA += __shfl_down_sync(0xffffffffu, aA, o);
        aB += __shfl_down_sync(0xffffffffu, aB, o);
    }
    __syncthreads();
    float* red = (float*)HS;
    if (lane == 0) { red[wid] = aI; red[16 + wid] = aA; red[32 + wid] = aB; }
    __syncthreads();
    __shared__ unsigned int sIsLast;
    if (tid == 0) {
        float I = 0.f, A = 0.f, B = 0.f;
        #pragma unroll
        for (int i = 0; i < 16; i++) { I += red[i]; A += red[16 + i]; B += red[32 + i]; }
        g_part[blockIdx.x * 3 + 0] = I;
        g_part[blockIdx.x * 3 + 1] = A;
        g_part[blockIdx.x * 3 + 2] = B;
        __threadfence();
        sIsLast = (atomicAdd(&g_count, 1u) == gridDim.x - 1u);
    }
    __syncthreads();

    if (sIsLast) {
        const int nbk = gridDim.x;
        float i = 0.f, a = 0.f, b = 0.f;
        for (int j = tid; j < nbk; j += 512) {
            i += g_part[3 * j + 0];
            a += g_part[3 * j + 1];
            b += g_part[3 * j + 2];
        }
        #pragma unroll
        for (int o = 16; o > 0; o >>= 1) {
            i += __shfl_down_sync(0xffffffffu, i, o);
            a += __shfl_down_sync(0xffffffffu, a, o);
            b += __shfl_down_sync(0xffffffffu, b, o);
        }
        __syncthreads();
        if (lane == 0) { red[wid] = i; red[16 + wid] = a; red[32 + wid] = b; }
        __syncthreads();
        if (tid == 0) {
            float I = 0.f, A = 0.f, B = 0.f;
            #pragma unroll
            for (int q = 0; q < 16; q++) { I += red[q]; A += red[16 + q]; B += red[32 + q]; }
            out[0] = 1.f - (2.f * I + 1.f) / (A + B + 1.f);
            g_count = 0;
        }
    }
}

extern "C" void kernel_launch(void* const* d_in, const int* in_sizes, int n_in,
                              void* d_out, int out_size)
{
    const float* input  = (const float*)d_in[0];
    const float* target = (const float*)d_in[1];
    const int nImg   = in_sizes[0] / (Hd * Wd);
    const int nBands = nImg * (Hd / 16);            // 2048 for B=64

    int sms = 148;
    cudaDeviceGetAttribute(&sms, cudaDevAttrMultiProcessorCount, 0);
    int grid = 2 * sms;                             // one balanced wave at occ-2
    if (grid > nBands) grid = nBands;
    if (grid > 1024) grid = 1024;                   // g_part capacity

    const size_t smem = (size_t)RING * Wd * sizeof(__half);   // 65536 B
    cudaFuncSetAttribute(wdice_main,
                         cudaFuncAttributeMaxDynamicSharedMemorySize, (int)smem);
    wdice_main<<<grid, 512, smem>>>(input, target, nBands, (float*)d_out);
}

// round 14
// speedup vs baseline: 1.1107x; 1.1107x over previous
#include <cuda_runtime.h>
#include <cuda_fp16.h>

// WeightedDiceLoss (sm_103a) — balanced band partition (grid = 2*SMs) with
// STATIC ring addressing: guard-free chunks processed in groups of 4 so ring
// bases are compile-time (0/16/32/48); only the final chunk per segment uses
// a runtime base. fp16 swizzled hsum ring (RING=64), one barrier per chunk,
// local 3-lane hsum producer.
// weight = 1 + 5*|boxavg31(target) - target|, zero pad, /961
// out = 1 - (2*sum(in*t*w) + 1) / (sum(in*w) + sum(t*w) + 1)

#define Wd    512
#define Hd    512
#define HALO  15
#define RING  64
#define INV_KK2 (1.0f/961.0f)

__device__ float g_part[3 * 1024];
__device__ unsigned int g_count = 0;

__global__ __launch_bounds__(512, 2)
void wdice_main(const float* __restrict__ input,
                const float* __restrict__ target,
                int nBands,                       // 16-row bands total
                float* __restrict__ out)
{
    extern __shared__ __half HS[];          // [RING][512] swizzled fp16 hsum
    const int tid  = threadIdx.x;
    const int wid  = tid >> 5;
    const int lane = tid & 31;
    const int G    = gridDim.x;

    const int c = tid;
    const int u = c >> 3;
    const int qoff = (u ^ ((u >> 3) & 7)) * 16 + (c & 7) * 2;
    const char* HSb = (const char*)HS;

    float aI = 0.f, aA = 0.f, aB = 0.f;

    int b0 = (int)(((long long)blockIdx.x * nBands) / G);
    const int b1 = (int)(((long long)(blockIdx.x + 1) * nBands) / G);

    while (b0 < b1) {
        const int img    = b0 >> 5;                 // 32 bands per image
        const int segEnd = min(b1, (img + 1) << 5);
        const int nb     = segEnd - b0;
        const int r0     = (b0 & 31) * 16;
        const int R      = nb * 16;
        const size_t imgOff = (size_t)img * (size_t)(Hd * Wd);

        auto produce = [&](int pr) {
            const int j = pr + wid;                 // 16 rows per call
            if (j >= R + 2 * HALO) return;
            const int gr = r0 - HALO + j;
            uint4* dstRow = (uint4*)((char*)HS + (size_t)(j & (RING - 1)) * 1024);
            const int key = (lane >> 2) & 7;
            if (gr < 0 || gr >= Hd) {
                const uint4 z = make_uint4(0, 0, 0, 0);
                dstRow[(2 * lane)     ^ key] = z;
                dstRow[(2 * lane + 1) ^ key] = z;
                return;
            }
            float p[16];
            const float4* row = (const float4*)(target + imgOff + (size_t)gr * Wd);
            #pragma unroll
            for (int q = 0; q < 4; q++) {
                float4 f = row[lane * 4 + q];
                p[4*q+0] = f.x; p[4*q+1] = f.y; p[4*q+2] = f.z; p[4*q+3] = f.w;
            }
            #pragma unroll
            for (int i = 1; i < 16; i++) p[i] += p[i-1];
            const float T  = p[15];
            float Tp = __shfl_up_sync(0xffffffffu, T, 1);
            if (lane == 0) Tp = 0.f;
            const float base = Tp + T;
            float h[16];
            #pragma unroll
            for (int i = 0; i < 16; i++) {
                float pm = __shfl_up_sync(0xffffffffu, p[i], 1);
                if (lane == 0) pm = 0.f;
                h[i] = base - pm;
            }
            #pragma unroll
            for (int i = 1; i < 16; i++) {
                float pp = __shfl_down_sync(0xffffffffu, p[i-1], 1);
                if (lane == 31) pp = 0.f;
                h[i] += pp;
            }
            unsigned up[8];
            #pragma unroll
            for (int q = 0; q < 8; q++) {
                __half2 hh = __floats2half2_rn(h[2*q], h[2*q+1]);
                up[q] = *reinterpret_cast<unsigned*>(&hh);
            }
            dstRow[(2 * lane)     ^ key] = make_uint4(up[0], up[1], up[2], up[3]);
            dstRow[(2 * lane + 1) ^ key] = make_uint4(up[4], up[5], up[6], up[7]);
        };

        produce(0); produce(16); produce(32); produce(48);
        __syncthreads();

        float vsum = 0.f;
        #pragma unroll
        for (int j = 0; j <= 2 * HALO; j++)
            vsum += __half2float(*(const __half*)(HSb + j * 1024 + qoff));

        const float* tgtK = target + imgOff + (size_t)r0 * Wd + c;
        const float* inpK = input  + imgOff + (size_t)r0 * Wd + c;

#define ROWOP(t_, in_) { \
        const float w_  = fmaf(5.f, fabsf(fmaf(vsum, INV_KK2, -(t_))), 1.f); \
        const float tw_ = (t_) * w_; \
        aI = fmaf((in_), tw_, aI); \
        aA = fmaf((in_), w_,  aA); \
        aB += tw_; }

#define VUP(ja_, js_) \
        vsum += __half2float(*(const __half*)(HSb + (ja_) * 1024 + qoff)) \
              - __half2float(*(const __half*)(HSb + (js_) * 1024 + qoff));

        // guard-free chunk: static ring base B, then advance pointers
#define CONSUME_FULL(B) { \
        _Pragma("unroll") \
        for (int kk = 0; kk < 16; kk++) { \
            const float t_  = tgtK[kk * Wd]; \
            const float in_ = inpK[kk * Wd]; \
            ROWOP(t_, in_); \
            VUP(((B) + 31 + kk) & (RING - 1), ((B) + kk) & (RING - 1)); \
        } \
        tgtK += 16 * Wd; inpK += 16 * Wd; }

        const int nf = nb - 1;                     // guard-free chunk count
        int ch = 0;
        while (ch + 4 <= nf) {                     // ch stays ≡ 0 (mod 4)
            CONSUME_FULL(0);  __syncthreads(); produce(64 + 16 * ch);
            CONSUME_FULL(16); __syncthreads(); produce(64 + 16 * (ch + 1));
            CONSUME_FULL(32); __syncthreads(); produce(64 + 16 * (ch + 2));
            CONSUME_FULL(48); __syncthreads(); produce(64 + 16 * (ch + 3));
            ch += 4;
        }
        const int rem = nf - ch;                   // 0..3, bases static again
        if (rem >= 1) { CONSUME_FULL(0);  __syncthreads(); produce(64 + 16 * ch); ch++; }
        if (rem >= 2) { CONSUME_FULL(16); __syncthreads(); produce(64 + 16 * ch); ch++; }
        if (rem >= 3) { CONSUME_FULL(32); __syncthreads(); produce(64 + 16 * ch); ch++; }

        {   // final chunk (ch == nb-1): runtime base, static kk<15 guard
            const int B = (ch * 16) & (RING - 1);
            #pragma unroll
            for (int kk = 0; kk < 16; kk++) {
                const float t_  = tgtK[kk * Wd];
                const float in_ = inpK[kk * Wd];
                ROWOP(t_, in_);
                if (kk < 15) { VUP((B + 31 + kk) & (RING - 1), (B + kk) & (RING - 1)); }
            }
            __syncthreads();                       // ring safe for next segment
        }
        b0 = segEnd;
    }

    // ---- Block reduction (fixed order -> deterministic)
    #pragma unroll
    for (int o = 16; o > 0; o >>= 1) {
        aI += __shfl_down_sync(0xffffffffu, aI, o);
        aA += __shfl_down_sync(0xffffffffu, aA, o);
        aB += __shfl_down_sync(0xffffffffu, aB, o);
    }
    float* red = (float*)HS;
    if (lane == 0) { red[wid] = aI; red[16 + wid] = aA; red[32 + wid] = aB; }
    __syncthreads();
    __shared__ unsigned int sIsLast;
    if (tid == 0) {
        float I = 0.f, A = 0.f, B = 0.f;
        #pragma unroll
        for (int i = 0; i < 16; i++) { I += red[i]; A += red[16 + i]; B += red[32 + i]; }
        g_part[blockIdx.x * 3 + 0] = I;
        g_part[blockIdx.x * 3 + 1] = A;
        g_part[blockIdx.x * 3 + 2] = B;
        __threadfence();
        sIsLast = (atomicAdd(&g_count, 1u) == gridDim.x - 1u);
    }
    __syncthreads();

    if (sIsLast) {
        const int nbk = gridDim.x;
        float i = 0.f, a = 0.f, b = 0.f;
        for (int j = tid; j < nbk; j += 512) {
            i += g_part[3 * j + 0];
            a += g_part[3 * j + 1];
            b += g_part[3 * j + 2];
        }
        #pragma unroll
        for (int o = 16; o > 0; o >>= 1) {
            i += __shfl_down_sync(0xffffffffu, i, o);
            a += __shfl_down_sync(0xffffffffu, a, o);
            b += __shfl_down_sync(0xffffffffu, b, o);
        }
        __syncthreads();
        if (lane == 0) { red[wid] = i; red[16 + wid] = a; red[32 + wid] = b; }
        __syncthreads();
        if (tid == 0) {
            float I = 0.f, A = 0.f, B = 0.f;
            #pragma unroll
            for (int q = 0; q < 16; q++) { I += red[q]; A += red[16 + q]; B += red[32 + q]; }
            out[0] = 1.f - (2.f * I + 1.f) / (A + B + 1.f);
            g_count = 0;
        }
    }
}

extern "C" void kernel_launch(void* const* d_in, const int* in_sizes, int n_in,
                              void* d_out, int out_size)
{
    const float* input  = (const float*)d_in[0];
    const float* target = (const float*)d_in[1];
    const int nImg   = in_sizes[0] / (Hd * Wd);
    const int nBands = nImg * (Hd / 16);            // 2048 for B=64

    int sms = 148;
    cudaDeviceGetAttribute(&sms, cudaDevAttrMultiProcessorCount, 0);
    int grid = 2 * sms;
    if (grid > nBands) grid = nBands;
    if (grid > 1024) grid = 1024;                   // g_part capacity

    const size_t smem = (size_t)RING * Wd * sizeof(__half);   // 65536 B
    cudaFuncSetAttribute(wdice_main,
                         cudaFuncAttributeMaxDynamicSharedMemorySize, (int)smem);
    wdice_main<<<grid, 512, smem>>>(input, target, nBands, (float*)d_out);
}

// round 15
// speedup vs baseline: 1.1420x; 1.0282x over previous
#include <cuda_runtime.h>
#include <cuda_fp16.h>

// WeightedDiceLoss (sm_103a) — fp16 swizzled ring RING=96 (96KB, occ-2),
// 5 barriers per CTA, interleaved produce/consume, fully static addressing.
// weight = 1 + 5*|boxavg31(target) - target|, zero pad, /961
// out = 1 - (2*sum(in*t*w) + 1) / (sum(in*w) + sum(t*w) + 1)

#define Wd    512
#define Hd    512
#define Rr    128
#define HALO  15
#define SLABR (Rr + 2*HALO)        // 158
#define RING  96                   // fp16 rows of 1KB -> 96KB
#define INV_KK2 (1.0f/961.0f)

__device__ float g_part[3 * 1024];
__device__ unsigned int g_count = 0;

__global__ __launch_bounds__(512, 2)
void wdice_main(const float* __restrict__ input,
                const float* __restrict__ target,
                float* __restrict__ out)
{
    extern __shared__ __half HS[];          // [RING][512] swizzled fp16 hsum
    const int tid  = threadIdx.x;
    const int wid  = tid >> 5;
    const int lane = tid & 31;
    const int img  = blockIdx.x >> 2;       // 4 slabs per image
    const int slab = blockIdx.x & 3;
    const int r0   = slab * Rr;
    const size_t imgOff = (size_t)img * (size_t)(Hd * Wd);

    // Produce hsum of slab row (prRow+wid) into ring slot (prSlot+wid).
    // prRow/prSlot are compile-time; inline LDG + local 3-lane hsum + STS.128.
    auto produce = [&](int prRow, int prSlot) {
        const int j = prRow + wid;                  // 16 rows per call
        if (j >= SLABR) return;
        const int gr = r0 - HALO + j;
        uint4* dstRow = (uint4*)((char*)HS + (size_t)(prSlot + wid) * 1024);
        const int key = (lane >> 2) & 7;
        if (gr < 0 || gr >= Hd) {
            const uint4 z = make_uint4(0, 0, 0, 0);
            dstRow[(2 * lane)     ^ key] = z;
            dstRow[(2 * lane + 1) ^ key] = z;
            return;
        }
        float p[16];
        const float4* row = (const float4*)(target + imgOff + (size_t)gr * Wd);
        #pragma unroll
        for (int q = 0; q < 4; q++) {
            float4 f = row[lane * 4 + q];
            p[4*q+0] = f.x; p[4*q+1] = f.y; p[4*q+2] = f.z; p[4*q+3] = f.w;
        }
        #pragma unroll
        for (int i = 1; i < 16; i++) p[i] += p[i-1];
        const float T  = p[15];
        float Tp = __shfl_up_sync(0xffffffffu, T, 1);
        if (lane == 0) Tp = 0.f;
        const float base = Tp + T;
        float h[16];
        #pragma unroll
        for (int i = 0; i < 16; i++) {
            float pm = __shfl_up_sync(0xffffffffu, p[i], 1);
            if (lane == 0) pm = 0.f;
            h[i] = base - pm;
        }
        #pragma unroll
        for (int i = 1; i < 16; i++) {
            float pp = __shfl_down_sync(0xffffffffu, p[i-1], 1);
            if (lane == 31) pp = 0.f;
            h[i] += pp;
        }
        unsigned up[8];
        #pragma unroll
        for (int q = 0; q < 8; q++) {
            __half2 hh = __floats2half2_rn(h[2*q], h[2*q+1]);
            up[q] = *reinterpret_cast<unsigned*>(&hh);
        }
        dstRow[(2 * lane)     ^ key] = make_uint4(up[0], up[1], up[2], up[3]);
        dstRow[(2 * lane + 1) ^ key] = make_uint4(up[4], up[5], up[6], up[7]);
    };

    // ---- Prime ring with slab rows 0..95.
    produce(0, 0);  produce(16, 16); produce(32, 32);
    produce(48, 48); produce(64, 64); produce(80, 80);
    __syncthreads();

    // ---- Consumer state: thread = column c, fixed swizzled byte offset.
    const int c = tid;
    const int u = c >> 3;
    const int qoff = (u ^ ((u >> 3) & 7)) * 16 + (c & 7) * 2;
    const char* HSb = (const char*)HS;

    float vsum = 0.f;
    #pragma unroll
    for (int j = 0; j <= 2 * HALO; j++)
        vsum += __half2float(*(const __half*)(HSb + j * 1024 + qoff));

    float aI = 0.f, aA = 0.f, aB = 0.f;
    const float* tgtK = target + imgOff + (size_t)r0 * Wd + c;
    const float* inpK = input  + imgOff + (size_t)r0 * Wd + c;

    // Chunk CH (0..7): rows 16CH..16CH+15, ring base (16*CH)%96 — all static.
#define CONSUME(CH) { \
        _Pragma("unroll") \
        for (int kk = 0; kk < 16; kk++) { \
            const float t_  = tgtK[kk * Wd]; \
            const float in_ = inpK[kk * Wd]; \
            const float w_  = fmaf(5.f, fabsf(fmaf(vsum, INV_KK2, -t_)), 1.f); \
            const float tw_ = t_ * w_; \
            aI = fmaf(in_, tw_, aI); \
            aA = fmaf(in_, w_,  aA); \
            aB += tw_; \
            if (!((CH) == 7 && kk == 15)) { \
                const int ja_ = ((16 * (CH)) % RING + 31 + kk) % RING; \
                const int js_ = ((16 * (CH)) % RING + kk) % RING; \
                vsum += __half2float(*(const __half*)(HSb + ja_ * 1024 + qoff)) \
                      - __half2float(*(const __half*)(HSb + js_ * 1024 + qoff)); \
            } \
        } \
        tgtK += 16 * Wd; inpK += 16 * Wd; }

    // Schedule (RAW/WAR verified; 5 barriers total):
    CONSUME(0); CONSUME(1);
    __syncthreads();
    produce(96, 0);   CONSUME(2); produce(112, 16); CONSUME(3);
    __syncthreads();
    produce(128, 32); CONSUME(4); produce(144, 48); CONSUME(5);
    __syncthreads();
    CONSUME(6); CONSUME(7);

    // ---- Block reduction (fixed order -> deterministic)
    #pragma unroll
    for (int o = 16; o > 0; o >>= 1) {
        aI += __shfl_down_sync(0xffffffffu, aI, o);
        aA += __shfl_down_sync(0xffffffffu, aA, o);
        aB += __shfl_down_sync(0xffffffffu, aB, o);
    }
    __syncthreads();                        // ring dead; reuse as scratch
    float* red = (float*)HS;
    if (lane == 0) { red[wid] = aI; red[16 + wid] = aA; red[32 + wid] = aB; }
    __syncthreads();
    __shared__ unsigned int sIsLast;
    if (tid == 0) {
        float I = 0.f, A = 0.f, B = 0.f;
        #pragma unroll
        for (int i = 0; i < 16; i++) { I += red[i]; A += red[16 + i]; B += red[32 + i]; }
        g_part[blockIdx.x * 3 + 0] = I;
        g_part[blockIdx.x * 3 + 1] = A;
        g_part[blockIdx.x * 3 + 2] = B;
        __threadfence();
        sIsLast = (atomicAdd(&g_count, 1u) == gridDim.x - 1u);
    }
    __syncthreads();

    if (sIsLast) {
        const int nbk = gridDim.x;
        float i = 0.f, a = 0.f, b = 0.f;
        for (int j = tid; j < nbk; j += 512) {
            i += g_part[3 * j + 0];
            a += g_part[3 * j + 1];
            b += g_part[3 * j + 2];
        }
        #pragma unroll
        for (int o = 16; o > 0; o >>= 1) {
            i += __shfl_down_sync(0xffffffffu, i, o);
            a += __shfl_down_sync(0xffffffffu, a, o);
            b += __shfl_down_sync(0xffffffffu, b, o);
        }
        __syncthreads();
        if (lane == 0) { red[wid] = i; red[16 + wid] = a; red[32 + wid] = b; }
        __syncthreads();
        if (tid == 0) {
            float I = 0.f, A = 0.f, B = 0.f;
            #pragma unroll
            for (int q = 0; q < 16; q++) { I += red[q]; A += red[16 + q]; B += red[32 + q]; }
            out[0] = 1.f - (2.f * I + 1.f) / (A + B + 1.f);
            g_count = 0;
        }
    }
}

extern "C" void kernel_launch(void* const* d_in, const int* in_sizes, int n_in,
                              void* d_out, int out_size)
{
    const float* input  = (const float*)d_in[0];
    const float* target = (const float*)d_in[1];
    const int nImg = in_sizes[0] / (Hd * Wd);
    const int grid = nImg * (Hd / Rr);              // 256
    const size_t smem = (size_t)RING * Wd * sizeof(__half);   // 98304 B

    cudaFuncSetAttribute(wdice_main,
                         cudaFuncAttributeMaxDynamicSharedMemorySize, (int)smem);
    wdice_main<<<grid, 512, smem>>>(input, target, (float*)d_out);
}

// round 16
// speedup vs baseline: 1.1617x; 1.0172x over previous
#include <cuda_runtime.h>
#include <cuda_fp16.h>

// WeightedDiceLoss (sm_103a) — fp16 swizzled ring RING=96, 4 mainloop
// barriers, producer LDGs prefetched one chunk ahead, static addressing.
// weight = 1 + 5*|boxavg31(target) - target|, zero pad, /961
// out = 1 - (2*sum(in*t*w) + 1) / (sum(in*w) + sum(t*w) + 1)

#define Wd    512
#define Hd    512
#define Rr    128
#define HALO  15
#define SLABR (Rr + 2*HALO)        // 158
#define RING  96                   // fp16 rows of 1KB -> 96KB
#define INV_KK2 (1.0f/961.0f)

__device__ float g_part[3 * 1024];
__device__ unsigned int g_count = 0;

__global__ __launch_bounds__(512, 2)
void wdice_main(const float* __restrict__ input,
                const float* __restrict__ target,
                float* __restrict__ out)
{
    extern __shared__ __half HS[];          // [RING][512] swizzled fp16 hsum
    const int tid  = threadIdx.x;
    const int wid  = tid >> 5;
    const int lane = tid & 31;
    const int img  = blockIdx.x >> 2;       // 4 slabs per image
    const int slab = blockIdx.x & 3;
    const int r0   = slab * Rr;
    const size_t imgOff = (size_t)img * (size_t)(Hd * Wd);

    // LDG slab row (prRow+wid) into regs (zeros outside image / past slab).
    auto pref = [&](int prRow, float v[16]) {
        const int j  = prRow + wid;
        const int gr = r0 - HALO + j;
        if (j < SLABR && gr >= 0 && gr < Hd) {
            const float4* row = (const float4*)(target + imgOff + (size_t)gr * Wd);
            #pragma unroll
            for (int q = 0; q < 4; q++) {
                float4 f = row[lane * 4 + q];
                v[4*q+0] = f.x; v[4*q+1] = f.y; v[4*q+2] = f.z; v[4*q+3] = f.w;
            }
        } else {
            #pragma unroll
            for (int i = 0; i < 16; i++) v[i] = 0.f;
        }
    };

    // Local 3-lane hsum from regs -> fp16 -> swizzled STS.128 at prSlot+wid.
    auto scanStore = [&](int prSlot, float p[16]) {
        uint4* dstRow = (uint4*)((char*)HS + (size_t)(prSlot + wid) * 1024);
        const int key = (lane >> 2) & 7;
        #pragma unroll
        for (int i = 1; i < 16; i++) p[i] += p[i-1];
        const float T  = p[15];
        float Tp = __shfl_up_sync(0xffffffffu, T, 1);
        if (lane == 0) Tp = 0.f;
        const float base = Tp + T;
        float h[16];
        #pragma unroll
        for (int i = 0; i < 16; i++) {
            float pm = __shfl_up_sync(0xffffffffu, p[i], 1);
            if (lane == 0) pm = 0.f;
            h[i] = base - pm;
        }
        #pragma unroll
        for (int i = 1; i < 16; i++) {
            float pp = __shfl_down_sync(0xffffffffu, p[i-1], 1);
            if (lane == 31) pp = 0.f;
            h[i] += pp;
        }
        unsigned up[8];
        #pragma unroll
        for (int q = 0; q < 8; q++) {
            __half2 hh = __floats2half2_rn(h[2*q], h[2*q+1]);
            up[q] = *reinterpret_cast<unsigned*>(&hh);
        }
        dstRow[(2 * lane)     ^ key] = make_uint4(up[0], up[1], up[2], up[3]);
        dstRow[(2 * lane + 1) ^ key] = make_uint4(up[4], up[5], up[6], up[7]);
    };

    // ---- Prime ring rows 0..95 (two-buffer LDG/scan overlap).
    float pw[16];
    {
        float pa[16];
        pref(0,  pa); pref(16, pw);
        scanStore(0,  pa); pref(32, pa);
        scanStore(16, pw); pref(48, pw);
        scanStore(32, pa); pref(64, pa);
        scanStore(48, pw); pref(80, pw);
        scanStore(64, pa);
        scanStore(80, pw);
    }
    __syncthreads();                                   // BAR0

    // ---- Consumer state: thread = column c, fixed swizzled byte offset.
    const int c = tid;
    const int u = c >> 3;
    const int qoff = (u ^ ((u >> 3) & 7)) * 16 + (c & 7) * 2;
    const char* HSb = (const char*)HS;

    float vsum = 0.f;
    #pragma unroll
    for (int j = 0; j <= 2 * HALO; j++)
        vsum += __half2float(*(const __half*)(HSb + j * 1024 + qoff));

    float aI = 0.f, aA = 0.f, aB = 0.f;
    const float* tgtK = target + imgOff + (size_t)r0 * Wd + c;
    const float* inpK = input  + imgOff + (size_t)r0 * Wd + c;

    // Chunk CH (0..7): rows 16CH..16CH+15, ring base (16*CH)%96 — static.
#define CONSUME(CH) { \
        _Pragma("unroll") \
        for (int kk = 0; kk < 16; kk++) { \
            const float t_  = tgtK[kk * Wd]; \
            const float in_ = inpK[kk * Wd]; \
            const float w_  = fmaf(5.f, fabsf(fmaf(vsum, INV_KK2, -t_)), 1.f); \
            const float tw_ = t_ * w_; \
            aI = fmaf(in_, tw_, aI); \
            aA = fmaf(in_, w_,  aA); \
            aB += tw_; \
            if (!((CH) == 7 && kk == 15)) { \
                const int ja_ = ((16 * (CH)) % RING + 31 + kk) % RING; \
                const int js_ = ((16 * (CH)) % RING + kk) % RING; \
                vsum += __half2float(*(const __half*)(HSb + ja_ * 1024 + qoff)) \
                      - __half2float(*(const __half*)(HSb + js_ * 1024 + qoff)); \
            } \
        } \
        tgtK += 16 * Wd; inpK += 16 * Wd; }

    // Pipelined schedule (RAW/WAR verified; 4 mainloop barriers):
    pref(96, pw);                       // rows 96..111, used after BAR1
    CONSUME(0); CONSUME(1);
    __syncthreads();                                   // BAR1
    scanStore(0, pw);  pref(112, pw);   // slots 0..15 <- rows 96..111
    CONSUME(2);
    scanStore(16, pw); pref(128, pw);   // slots 16..31 <- rows 112..127
    CONSUME(3);
    __syncthreads();                                   // BAR2
    scanStore(32, pw); pref(144, pw);   // slots 32..47 <- rows 128..143
    CONSUME(4);
    scanStore(48, pw);                  // slots 48..63 <- rows 144..157(9)
    CONSUME(5);
    __syncthreads();                                   // BAR3
    CONSUME(6); CONSUME(7);

    // ---- Block reduction (fixed order -> deterministic)
    #pragma unroll
    for (int o = 16; o > 0; o >>= 1) {
        aI += __shfl_down_sync(0xffffffffu, aI, o);
        aA += __shfl_down_sync(0xffffffffu, aA, o);
        aB += __shfl_down_sync(0xffffffffu, aB, o);
    }
    __syncthreads();                    // all consumes done; ring reusable
    float* red = (float*)HS;
    if (lane == 0) { red[wid] = aI; red[16 + wid] = aA; red[32 + wid] = aB; }
    __syncthreads();
    __shared__ unsigned int sIsLast;
    if (tid == 0) {
        float I = 0.f, A = 0.f, B = 0.f;
        #pragma unroll
        for (int i = 0; i < 16; i++) { I += red[i]; A += red[16 + i]; B += red[32 + i]; }
        g_part[blockIdx.x * 3 + 0] = I;
        g_part[blockIdx.x * 3 + 1] = A;
        g_part[blockIdx.x * 3 + 2] = B;
        __threadfence();
        sIsLast = (atomicAdd(&g_count, 1u) == gridDim.x - 1u);
    }
    __syncthreads();

    if (sIsLast) {
        const int nbk = gridDim.x;
        float i = 0.f, a = 0.f, b = 0.f;
        for (int j = tid; j < nbk; j += 512) {
            i += g_part[3 * j + 0];
            a += g_part[3 * j + 1];
            b += g_part[3 * j + 2];
        }
        #pragma unroll
        for (int o = 16; o > 0; o >>= 1) {
            i += __shfl_down_sync(0xffffffffu, i, o);
            a += __shfl_down_sync(0xffffffffu, a, o);
            b += __shfl_down_sync(0xffffffffu, b, o);
        }
        __syncthreads();
        if (lane == 0) { red[wid] = i; red[16 + wid] = a; red[32 + wid] = b; }
        __syncthreads();
        if (tid == 0) {
            float I = 0.f, A = 0.f, B = 0.f;
            #pragma unroll
            for (int q = 0; q < 16; q++) { I += red[q]; A += red[16 + q]; B += red[32 + q]; }
            out[0] = 1.f - (2.f * I + 1.f) / (A + B + 1.f);
            g_count = 0;
        }
    }
}

extern "C" void kernel_launch(void* const* d_in, const int* in_sizes, int n_in,
                              void* d_out, int out_size)
{
    const float* input  = (const float*)d_in[0];
    const float* target = (const float*)d_in[1];
    const int nImg = in_sizes[0] / (Hd * Wd);
    const int grid = nImg * (Hd / Rr);              // 256
    const size_t smem = (size_t)RING * Wd * sizeof(__half);   // 98304 B

    cudaFuncSetAttribute(wdice_main,
                         cudaFuncAttributeMaxDynamicSharedMemorySize, (int)smem);
    wdice_main<<<grid, 512, smem>>>(input, target, (float*)d_out);
}